// round 1
// baseline (speedup 1.0000x reference)
#include <cuda_runtime.h>

// PureCartesianTensorProductO3Sparse — factorized fused kernel.
//
// Per row n (only s=0 blocks used):
//   A0[16]       = x1[n, 0:16]
//   A1[16][3]    = x1[n, 16:64]
//   A2[16][9]    = x1[n, 64:208]
//   B0,B1,B2       likewise from x2
// Paths (weight layout per path: W[o][a][b], 16^3):
//   p0 (0,0): out0[o]     += sum_ab A0[a] B0[b]    W0
//   p1 (0,1): out1[o,i]   += sum_ab A0[a] B1[b,i]  W1
//   p2 (0,2): out2[o,ij]  += sum_ab A0[a] B2[b,ij] W2
//   p3 (1,0): out1[o,i]   += sum_ab A1[a,i] B0[b]  W3
//   p4 (1,1): out2[o,ij]  += sum_ab A1[a,i] B1[b,j] W4
//   p5 (2,0): out2[o,ij]  += sum_ab A2[a,ij] B0[b] W5
// Factorized: contract the scalar (L=0) operand (or A1 over b for p4) with W
// first -> 41.5k MACs/row instead of 139k.

constexpr int NPATH    = 6;
constexpr int CC       = 16;
constexpr int WELEMS   = NPATH * CC * CC * CC;   // 24576
constexpr int BPAD     = 20;                     // padded b-stride (bank spread)
constexpr int WSM      = NPATH * CC * CC * BPAD; // 30720 floats in smem
constexpr int ROW_IN   = 416;
constexpr int ROW_USED = 208;
constexpr int RPT      = 16;                     // rows per tile
constexpr int THREADS  = 256;

// smem weight index: [p][a][o][b(padded)]
__device__ __forceinline__ int ws_idx(int p, int a, int o) {
    return ((p * 256) + (a * 16) + o) * BPAD;
}

__global__ __launch_bounds__(THREADS, 1)
void tp_o3_kernel(const float* __restrict__ x1,
                  const float* __restrict__ x2,
                  const float* __restrict__ wgt,
                  float* __restrict__ out,
                  int N)
{
    extern __shared__ float smem[];
    float* ws  = smem;                    // 30720 floats
    float* x1s = smem + WSM;              // 16 x 208
    float* x2s = x1s + RPT * ROW_USED;    // 16 x 208

    const int tid = threadIdx.x;

    // Load + transpose weights: gmem [p][o][a][b] -> smem [p][a][o][b_pad]
    for (int idx = tid; idx < WELEMS; idx += THREADS) {
        int p = idx >> 12;
        int o = (idx >> 8) & 15;
        int a = (idx >> 4) & 15;
        int b = idx & 15;
        ws[ws_idx(p, a, o) + b] = wgt[idx];
    }
    __syncthreads();

    const int o    = tid & 15;   // output channel owned by this thread
    const int slot = tid >> 4;   // row slot within tile (0..15)
    const int ntiles = (N + RPT - 1) / RPT;

    for (int tile = blockIdx.x; tile < ntiles; tile += (int)gridDim.x) {
        const int row0  = tile * RPT;
        const int nrows = min(RPT, N - row0);

        // ---- stage the used halves of x1/x2 rows into smem (float4) ----
        {
            const float4* g1 = reinterpret_cast<const float4*>(x1) + (size_t)row0 * 104;
            const float4* g2 = reinterpret_cast<const float4*>(x2) + (size_t)row0 * 104;
            float4* s1 = reinterpret_cast<float4*>(x1s);
            float4* s2 = reinterpret_cast<float4*>(x2s);
            for (int i = tid; i < nrows * 52; i += THREADS) {
                int r = i / 52, c = i - r * 52;
                s1[r * 52 + c] = g1[(size_t)r * 104 + c];
                s2[r * 52 + c] = g2[(size_t)r * 104 + c];
            }
        }
        __syncthreads();

        if (slot < nrows) {
            const float* xa = x1s + slot * ROW_USED;
            const float* xb = x2s + slot * ROW_USED;

            float acc0 = 0.f;
            float acc1[3] = {0.f, 0.f, 0.f};
            float acc2[9] = {0.f, 0.f, 0.f, 0.f, 0.f, 0.f, 0.f, 0.f, 0.f};

            float A0[16];
            #pragma unroll
            for (int a = 0; a < 16; a++) A0[a] = xa[a];

            // helper: t[b] = sum_a A0[a] * W[p][a][o][b]
            auto stage1A = [&](int p, float (&t)[16]) {
                #pragma unroll
                for (int b = 0; b < 16; b++) t[b] = 0.f;
                const float* wp = ws + ws_idx(p, 0, o);
                #pragma unroll
                for (int a = 0; a < 16; a++) {
                    const float4* wv = reinterpret_cast<const float4*>(wp + a * (16 * BPAD));
                    float4 q0 = wv[0], q1 = wv[1], q2 = wv[2], q3 = wv[3];
                    float av = A0[a];
                    t[0]  = fmaf(av, q0.x, t[0]);  t[1]  = fmaf(av, q0.y, t[1]);
                    t[2]  = fmaf(av, q0.z, t[2]);  t[3]  = fmaf(av, q0.w, t[3]);
                    t[4]  = fmaf(av, q1.x, t[4]);  t[5]  = fmaf(av, q1.y, t[5]);
                    t[6]  = fmaf(av, q1.z, t[6]);  t[7]  = fmaf(av, q1.w, t[7]);
                    t[8]  = fmaf(av, q2.x, t[8]);  t[9]  = fmaf(av, q2.y, t[9]);
                    t[10] = fmaf(av, q2.z, t[10]); t[11] = fmaf(av, q2.w, t[11]);
                    t[12] = fmaf(av, q3.x, t[12]); t[13] = fmaf(av, q3.y, t[13]);
                    t[14] = fmaf(av, q3.z, t[14]); t[15] = fmaf(av, q3.w, t[15]);
                }
            };

            // ---- path 0 (0,0): acc0 = sum_b t[b] * B0[b]
            {
                float t[16];
                stage1A(0, t);
                float u0 = 0.f, u1 = 0.f, u2 = 0.f, u3 = 0.f;
                #pragma unroll
                for (int b = 0; b < 16; b += 4) {
                    u0 = fmaf(t[b + 0], xb[b + 0], u0);
                    u1 = fmaf(t[b + 1], xb[b + 1], u1);
                    u2 = fmaf(t[b + 2], xb[b + 2], u2);
                    u3 = fmaf(t[b + 3], xb[b + 3], u3);
                }
                acc0 = (u0 + u1) + (u2 + u3);
            }

            // ---- path 1 (0,1): acc1[i] += t[b] * B1[b][i]
            {
                float t[16];
                stage1A(1, t);
                #pragma unroll
                for (int b = 0; b < 16; b++) {
                    float tb = t[b];
                    acc1[0] = fmaf(tb, xb[16 + 3 * b + 0], acc1[0]);
                    acc1[1] = fmaf(tb, xb[16 + 3 * b + 1], acc1[1]);
                    acc1[2] = fmaf(tb, xb[16 + 3 * b + 2], acc1[2]);
                }
            }

            // ---- path 2 (0,2): acc2[k] += t[b] * B2[b][k]
            {
                float t[16];
                stage1A(2, t);
                #pragma unroll
                for (int b = 0; b < 16; b++) {
                    float tb = t[b];
                    #pragma unroll
                    for (int k = 0; k < 9; k++)
                        acc2[k] = fmaf(tb, xb[64 + 9 * b + k], acc2[k]);
                }
            }

            // B0 cached for paths 3 & 5
            float B0[16];
            #pragma unroll
            for (int b = 0; b < 16; b++) B0[b] = xb[b];

            auto dotB0 = [&](const float* wa) -> float {
                const float4* wv = reinterpret_cast<const float4*>(wa);
                float4 q0 = wv[0], q1 = wv[1], q2 = wv[2], q3 = wv[3];
                float u0 = B0[0] * q0.x, u1 = B0[4] * q1.x,
                      u2 = B0[8] * q2.x, u3 = B0[12] * q3.x;
                u0 = fmaf(B0[1],  q0.y, u0); u0 = fmaf(B0[2],  q0.z, u0); u0 = fmaf(B0[3],  q0.w, u0);
                u1 = fmaf(B0[5],  q1.y, u1); u1 = fmaf(B0[6],  q1.z, u1); u1 = fmaf(B0[7],  q1.w, u1);
                u2 = fmaf(B0[9],  q2.y, u2); u2 = fmaf(B0[10], q2.z, u2); u2 = fmaf(B0[11], q2.w, u2);
                u3 = fmaf(B0[13], q3.y, u3); u3 = fmaf(B0[14], q3.z, u3); u3 = fmaf(B0[15], q3.w, u3);
                return (u0 + u1) + (u2 + u3);
            };

            // ---- path 3 (1,0): acc1[i] += s[a] * A1[a][i]
            {
                const float* wp = ws + ws_idx(3, 0, o);
                #pragma unroll
                for (int a = 0; a < 16; a++) {
                    float s = dotB0(wp + a * (16 * BPAD));
                    acc1[0] = fmaf(s, xa[16 + 3 * a + 0], acc1[0]);
                    acc1[1] = fmaf(s, xa[16 + 3 * a + 1], acc1[1]);
                    acc1[2] = fmaf(s, xa[16 + 3 * a + 2], acc1[2]);
                }
            }

            // ---- path 5 (2,0): acc2[k] += s[a] * A2[a][k]
            {
                const float* wp = ws + ws_idx(5, 0, o);
                #pragma unroll
                for (int a = 0; a < 16; a++) {
                    float s = dotB0(wp + a * (16 * BPAD));
                    #pragma unroll
                    for (int k = 0; k < 9; k++)
                        acc2[k] = fmaf(s, xa[64 + 9 * a + k], acc2[k]);
                }
            }

            // ---- path 4 (1,1): v[j] = sum_b W4[a][b] B1[b][j]; acc2[ij] += A1[a][i] v[j]
            {
                float B1t[3][16];
                #pragma unroll
                for (int b = 0; b < 16; b++) {
                    B1t[0][b] = xb[16 + 3 * b + 0];
                    B1t[1][b] = xb[16 + 3 * b + 1];
                    B1t[2][b] = xb[16 + 3 * b + 2];
                }
                const float* wp = ws + ws_idx(4, 0, o);
                #pragma unroll
                for (int a = 0; a < 16; a++) {
                    const float4* wv = reinterpret_cast<const float4*>(wp + a * (16 * BPAD));
                    float w[16];
                    float4 q0 = wv[0], q1 = wv[1], q2 = wv[2], q3 = wv[3];
                    w[0]=q0.x; w[1]=q0.y; w[2]=q0.z; w[3]=q0.w;
                    w[4]=q1.x; w[5]=q1.y; w[6]=q1.z; w[7]=q1.w;
                    w[8]=q2.x; w[9]=q2.y; w[10]=q2.z; w[11]=q2.w;
                    w[12]=q3.x; w[13]=q3.y; w[14]=q3.z; w[15]=q3.w;

                    float v0a=0.f, v0b=0.f, v1a=0.f, v1b=0.f, v2a=0.f, v2b=0.f;
                    #pragma unroll
                    for (int b = 0; b < 16; b += 2) {
                        v0a = fmaf(w[b],     B1t[0][b],     v0a);
                        v0b = fmaf(w[b + 1], B1t[0][b + 1], v0b);
                        v1a = fmaf(w[b],     B1t[1][b],     v1a);
                        v1b = fmaf(w[b + 1], B1t[1][b + 1], v1b);
                        v2a = fmaf(w[b],     B1t[2][b],     v2a);
                        v2b = fmaf(w[b + 1], B1t[2][b + 1], v2b);
                    }
                    float v0 = v0a + v0b, v1 = v1a + v1b, v2 = v2a + v2b;
                    float a10 = xa[16 + 3 * a + 0];
                    float a11 = xa[16 + 3 * a + 1];
                    float a12 = xa[16 + 3 * a + 2];
                    acc2[0] = fmaf(a10, v0, acc2[0]); acc2[1] = fmaf(a10, v1, acc2[1]); acc2[2] = fmaf(a10, v2, acc2[2]);
                    acc2[3] = fmaf(a11, v0, acc2[3]); acc2[4] = fmaf(a11, v1, acc2[4]); acc2[5] = fmaf(a11, v2, acc2[5]);
                    acc2[6] = fmaf(a12, v0, acc2[6]); acc2[7] = fmaf(a12, v1, acc2[7]); acc2[8] = fmaf(a12, v2, acc2[8]);
                }
            }

            // ---- write outputs (first half of the row)
            float* orow = out + (size_t)(row0 + slot) * ROW_IN;
            orow[o] = acc0;
            #pragma unroll
            for (int i = 0; i < 3; i++) orow[16 + 3 * o + i] = acc1[i];
            #pragma unroll
            for (int k = 0; k < 9; k++) orow[64 + 9 * o + k] = acc2[k];
        }

        // ---- zero the s=1 half (cols 208..415) cooperatively
        {
            float4 z = make_float4(0.f, 0.f, 0.f, 0.f);
            float4* og = reinterpret_cast<float4*>(out) + (size_t)row0 * 104;
            for (int i = tid; i < nrows * 52; i += THREADS) {
                int r = i / 52, c = i - r * 52;
                og[(size_t)r * 104 + 52 + c] = z;
            }
        }
        __syncthreads();   // protect smem staging reuse
    }
}

extern "C" void kernel_launch(void* const* d_in, const int* in_sizes, int n_in,
                              void* d_out, int out_size)
{
    const float* x1 = (const float*)d_in[0];
    const float* x2 = (const float*)d_in[1];
    const float* w  = (const float*)d_in[2];
    float* out = (float*)d_out;
    const int N = in_sizes[0] / ROW_IN;

    const int smem_bytes = (WSM + 2 * RPT * ROW_USED) * (int)sizeof(float);

    int smcount = 0;
    cudaDeviceGetAttribute(&smcount, cudaDevAttrMultiProcessorCount, 0);
    if (smcount <= 0) smcount = 148;
    cudaFuncSetAttribute(tp_o3_kernel, cudaFuncAttributeMaxDynamicSharedMemorySize,
                         smem_bytes);

    tp_o3_kernel<<<smcount, THREADS, smem_bytes>>>(x1, x2, w, out, N);
}

// round 2
// speedup vs baseline: 1.1096x; 1.1096x over previous
#include <cuda_runtime.h>

// PureCartesianTensorProductO3Sparse — factorized, 2-output-channels-per-thread.
//
// Warp shape: 8 o-lanes x 4 row-slots. Each thread computes output channels
// {olane, olane+8} for one row. Weight LDS.128 -> 8 distinct 16B addresses =
// 128B (1 crossbar cycle, conflict-free with BPAD=20), reused by 4 rows.
// Scalar x reads shared by both o's and 4 rows per warp instruction.

constexpr int NPATH    = 6;
constexpr int CC       = 16;
constexpr int WELEMS   = NPATH * CC * CC * CC;   // 24576
constexpr int BPAD     = 20;                     // padded b-stride
constexpr int WSM      = NPATH * CC * CC * BPAD; // 30720 floats
constexpr int ROW_IN   = 416;
constexpr int ROW_USED = 208;
constexpr int ROW_PAD  = 212;                    // staging stride (bank-friendly, /4)
constexpr int RPT      = 48;                     // rows per tile
constexpr int THREADS  = 384;                    // 12 warps

__device__ __forceinline__ int ws_idx(int p, int a, int o) {
    return ((p * 256) + (a * 16) + o) * BPAD;
}

__global__ __launch_bounds__(THREADS, 1)
void tp_o3_kernel(const float* __restrict__ x1,
                  const float* __restrict__ x2,
                  const float* __restrict__ wgt,
                  float* __restrict__ out,
                  int N)
{
    extern __shared__ float smem[];
    float* ws  = smem;                    // 30720
    float* x1s = smem + WSM;              // 48 x 212
    float* x2s = x1s + RPT * ROW_PAD;     // 48 x 212

    const int tid = threadIdx.x;

    // Load + transpose weights: gmem [p][o][a][b] -> smem [p][a][o][b_pad]
    for (int idx = tid; idx < WELEMS; idx += THREADS) {
        int p = idx >> 12;
        int o = (idx >> 8) & 15;
        int a = (idx >> 4) & 15;
        int b = idx & 15;
        ws[ws_idx(p, a, o) + b] = wgt[idx];
    }
    __syncthreads();

    const int olane = tid & 7;
    const int slot  = tid >> 3;          // 0..47
    const int o1 = olane, o2 = olane + 8;
    const int ntiles = (N + RPT - 1) / RPT;

    for (int tile = blockIdx.x; tile < ntiles; tile += (int)gridDim.x) {
        const int row0  = tile * RPT;
        const int nrows = min(RPT, N - row0);

        // ---- stage used halves of rows into smem (float4, padded stride) ----
        {
            const float4* g1 = reinterpret_cast<const float4*>(x1) + (size_t)row0 * 104;
            const float4* g2 = reinterpret_cast<const float4*>(x2) + (size_t)row0 * 104;
            float4* s1 = reinterpret_cast<float4*>(x1s);
            float4* s2 = reinterpret_cast<float4*>(x2s);
            for (int i = tid; i < nrows * 52; i += THREADS) {
                int r = i / 52, c = i - r * 52;
                s1[r * 53 + c] = g1[(size_t)r * 104 + c];
                s2[r * 53 + c] = g2[(size_t)r * 104 + c];
            }
        }
        __syncthreads();

        if (slot < nrows) {
            const float* xa = x1s + slot * ROW_PAD;
            const float* xb = x2s + slot * ROW_PAD;

            float acc0_1 = 0.f, acc0_2 = 0.f;
            float acc1_1[3] = {0.f,0.f,0.f}, acc1_2[3] = {0.f,0.f,0.f};
            float acc2_1[9] = {0.f,0.f,0.f,0.f,0.f,0.f,0.f,0.f,0.f};
            float acc2_2[9] = {0.f,0.f,0.f,0.f,0.f,0.f,0.f,0.f,0.f};

            float A0[16];
            #pragma unroll
            for (int a = 0; a < 16; a++) A0[a] = xa[a];

            // t1[b], t2[b] = sum_a A0[a] * W[p][a][o{1,2}][b]
            auto stage1 = [&](int p, float (&t1)[16], float (&t2)[16]) {
                #pragma unroll
                for (int b = 0; b < 16; b++) { t1[b] = 0.f; t2[b] = 0.f; }
                const float* w1 = ws + ws_idx(p, 0, o1);
                const float* w2 = ws + ws_idx(p, 0, o2);
                #pragma unroll
                for (int a = 0; a < 16; a++) {
                    float av = A0[a];
                    const float4* v1 = reinterpret_cast<const float4*>(w1 + a * (16 * BPAD));
                    const float4* v2 = reinterpret_cast<const float4*>(w2 + a * (16 * BPAD));
                    float4 q;
                    q = v1[0]; t1[0] =fmaf(av,q.x,t1[0]);  t1[1] =fmaf(av,q.y,t1[1]);
                               t1[2] =fmaf(av,q.z,t1[2]);  t1[3] =fmaf(av,q.w,t1[3]);
                    q = v1[1]; t1[4] =fmaf(av,q.x,t1[4]);  t1[5] =fmaf(av,q.y,t1[5]);
                               t1[6] =fmaf(av,q.z,t1[6]);  t1[7] =fmaf(av,q.w,t1[7]);
                    q = v1[2]; t1[8] =fmaf(av,q.x,t1[8]);  t1[9] =fmaf(av,q.y,t1[9]);
                               t1[10]=fmaf(av,q.z,t1[10]); t1[11]=fmaf(av,q.w,t1[11]);
                    q = v1[3]; t1[12]=fmaf(av,q.x,t1[12]); t1[13]=fmaf(av,q.y,t1[13]);
                               t1[14]=fmaf(av,q.z,t1[14]); t1[15]=fmaf(av,q.w,t1[15]);
                    q = v2[0]; t2[0] =fmaf(av,q.x,t2[0]);  t2[1] =fmaf(av,q.y,t2[1]);
                               t2[2] =fmaf(av,q.z,t2[2]);  t2[3] =fmaf(av,q.w,t2[3]);
                    q = v2[1]; t2[4] =fmaf(av,q.x,t2[4]);  t2[5] =fmaf(av,q.y,t2[5]);
                               t2[6] =fmaf(av,q.z,t2[6]);  t2[7] =fmaf(av,q.w,t2[7]);
                    q = v2[2]; t2[8] =fmaf(av,q.x,t2[8]);  t2[9] =fmaf(av,q.y,t2[9]);
                               t2[10]=fmaf(av,q.z,t2[10]); t2[11]=fmaf(av,q.w,t2[11]);
                    q = v2[3]; t2[12]=fmaf(av,q.x,t2[12]); t2[13]=fmaf(av,q.y,t2[13]);
                               t2[14]=fmaf(av,q.z,t2[14]); t2[15]=fmaf(av,q.w,t2[15]);
                }
            };

            // ---- path 0 (0,0)
            {
                float t1[16], t2[16];
                stage1(0, t1, t2);
                float u1a=0.f,u1b=0.f,u2a=0.f,u2b=0.f;
                #pragma unroll
                for (int b = 0; b < 16; b += 2) {
                    float xb0 = xb[b], xb1 = xb[b+1];
                    u1a = fmaf(t1[b],   xb0, u1a);
                    u1b = fmaf(t1[b+1], xb1, u1b);
                    u2a = fmaf(t2[b],   xb0, u2a);
                    u2b = fmaf(t2[b+1], xb1, u2b);
                }
                acc0_1 = u1a + u1b;
                acc0_2 = u2a + u2b;
            }

            // ---- path 1 (0,1)
            {
                float t1[16], t2[16];
                stage1(1, t1, t2);
                #pragma unroll
                for (int b = 0; b < 16; b++) {
                    float e0 = xb[16 + 3*b + 0];
                    float e1 = xb[16 + 3*b + 1];
                    float e2 = xb[16 + 3*b + 2];
                    acc1_1[0] = fmaf(t1[b], e0, acc1_1[0]);
                    acc1_1[1] = fmaf(t1[b], e1, acc1_1[1]);
                    acc1_1[2] = fmaf(t1[b], e2, acc1_1[2]);
                    acc1_2[0] = fmaf(t2[b], e0, acc1_2[0]);
                    acc1_2[1] = fmaf(t2[b], e1, acc1_2[1]);
                    acc1_2[2] = fmaf(t2[b], e2, acc1_2[2]);
                }
            }

            // ---- path 2 (0,2)
            {
                float t1[16], t2[16];
                stage1(2, t1, t2);
                #pragma unroll
                for (int b = 0; b < 16; b++) {
                    float tb1 = t1[b], tb2 = t2[b];
                    #pragma unroll
                    for (int k = 0; k < 9; k++) {
                        float e = xb[64 + 9*b + k];
                        acc2_1[k] = fmaf(tb1, e, acc2_1[k]);
                        acc2_2[k] = fmaf(tb2, e, acc2_2[k]);
                    }
                }
            }

            // ---- B0 in regs for paths 3 & 5
            float B0[16];
            #pragma unroll
            for (int b = 0; b < 16; b++) B0[b] = xb[b];

            auto dotB0 = [&](const float* wa) -> float {
                const float4* wv = reinterpret_cast<const float4*>(wa);
                float4 q0 = wv[0], q1 = wv[1], q2 = wv[2], q3 = wv[3];
                float u0 = B0[0]*q0.x, u1 = B0[4]*q1.x, u2 = B0[8]*q2.x, u3 = B0[12]*q3.x;
                u0 = fmaf(B0[1], q0.y,u0); u0 = fmaf(B0[2], q0.z,u0); u0 = fmaf(B0[3], q0.w,u0);
                u1 = fmaf(B0[5], q1.y,u1); u1 = fmaf(B0[6], q1.z,u1); u1 = fmaf(B0[7], q1.w,u1);
                u2 = fmaf(B0[9], q2.y,u2); u2 = fmaf(B0[10],q2.z,u2); u2 = fmaf(B0[11],q2.w,u2);
                u3 = fmaf(B0[13],q3.y,u3); u3 = fmaf(B0[14],q3.z,u3); u3 = fmaf(B0[15],q3.w,u3);
                return (u0 + u1) + (u2 + u3);
            };

            // ---- path 3 (1,0)
            {
                const float* w1 = ws + ws_idx(3, 0, o1);
                const float* w2 = ws + ws_idx(3, 0, o2);
                #pragma unroll
                for (int a = 0; a < 16; a++) {
                    float s1 = dotB0(w1 + a * (16 * BPAD));
                    float s2 = dotB0(w2 + a * (16 * BPAD));
                    float e0 = xa[16 + 3*a + 0];
                    float e1 = xa[16 + 3*a + 1];
                    float e2 = xa[16 + 3*a + 2];
                    acc1_1[0] = fmaf(s1, e0, acc1_1[0]);
                    acc1_1[1] = fmaf(s1, e1, acc1_1[1]);
                    acc1_1[2] = fmaf(s1, e2, acc1_1[2]);
                    acc1_2[0] = fmaf(s2, e0, acc1_2[0]);
                    acc1_2[1] = fmaf(s2, e1, acc1_2[1]);
                    acc1_2[2] = fmaf(s2, e2, acc1_2[2]);
                }
            }

            // ---- path 5 (2,0)
            {
                const float* w1 = ws + ws_idx(5, 0, o1);
                const float* w2 = ws + ws_idx(5, 0, o2);
                #pragma unroll
                for (int a = 0; a < 16; a++) {
                    float s1 = dotB0(w1 + a * (16 * BPAD));
                    float s2 = dotB0(w2 + a * (16 * BPAD));
                    #pragma unroll
                    for (int k = 0; k < 9; k++) {
                        float e = xa[64 + 9*a + k];
                        acc2_1[k] = fmaf(s1, e, acc2_1[k]);
                        acc2_2[k] = fmaf(s2, e, acc2_2[k]);
                    }
                }
            }

            // ---- path 4 (1,1): v{1,2}[j] = sum_b W4[o][a][b] B1[b][j]
            {
                float B1t[3][16];
                #pragma unroll
                for (int b = 0; b < 16; b++) {
                    B1t[0][b] = xb[16 + 3*b + 0];
                    B1t[1][b] = xb[16 + 3*b + 1];
                    B1t[2][b] = xb[16 + 3*b + 2];
                }
                const float* w1 = ws + ws_idx(4, 0, o1);
                const float* w2 = ws + ws_idx(4, 0, o2);
                #pragma unroll
                for (int a = 0; a < 16; a++) {
                    float v1j[3], v2j[3];
                    #pragma unroll
                    for (int oo = 0; oo < 2; oo++) {
                        const float* wp = (oo == 0 ? w1 : w2) + a * (16 * BPAD);
                        const float4* wv = reinterpret_cast<const float4*>(wp);
                        float w[16];
                        float4 q0 = wv[0], q1 = wv[1], q2 = wv[2], q3 = wv[3];
                        w[0]=q0.x; w[1]=q0.y; w[2]=q0.z; w[3]=q0.w;
                        w[4]=q1.x; w[5]=q1.y; w[6]=q1.z; w[7]=q1.w;
                        w[8]=q2.x; w[9]=q2.y; w[10]=q2.z; w[11]=q2.w;
                        w[12]=q3.x; w[13]=q3.y; w[14]=q3.z; w[15]=q3.w;
                        float v0a=0.f,v0b=0.f,v1a=0.f,v1b=0.f,v2a=0.f,v2b=0.f;
                        #pragma unroll
                        for (int b = 0; b < 16; b += 2) {
                            v0a = fmaf(w[b],   B1t[0][b],   v0a);
                            v0b = fmaf(w[b+1], B1t[0][b+1], v0b);
                            v1a = fmaf(w[b],   B1t[1][b],   v1a);
                            v1b = fmaf(w[b+1], B1t[1][b+1], v1b);
                            v2a = fmaf(w[b],   B1t[2][b],   v2a);
                            v2b = fmaf(w[b+1], B1t[2][b+1], v2b);
                        }
                        float* vj = (oo == 0) ? v1j : v2j;
                        vj[0] = v0a + v0b; vj[1] = v1a + v1b; vj[2] = v2a + v2b;
                    }
                    float a10 = xa[16 + 3*a + 0];
                    float a11 = xa[16 + 3*a + 1];
                    float a12 = xa[16 + 3*a + 2];
                    acc2_1[0]=fmaf(a10,v1j[0],acc2_1[0]); acc2_1[1]=fmaf(a10,v1j[1],acc2_1[1]); acc2_1[2]=fmaf(a10,v1j[2],acc2_1[2]);
                    acc2_1[3]=fmaf(a11,v1j[0],acc2_1[3]); acc2_1[4]=fmaf(a11,v1j[1],acc2_1[4]); acc2_1[5]=fmaf(a11,v1j[2],acc2_1[5]);
                    acc2_1[6]=fmaf(a12,v1j[0],acc2_1[6]); acc2_1[7]=fmaf(a12,v1j[1],acc2_1[7]); acc2_1[8]=fmaf(a12,v1j[2],acc2_1[8]);
                    acc2_2[0]=fmaf(a10,v2j[0],acc2_2[0]); acc2_2[1]=fmaf(a10,v2j[1],acc2_2[1]); acc2_2[2]=fmaf(a10,v2j[2],acc2_2[2]);
                    acc2_2[3]=fmaf(a11,v2j[0],acc2_2[3]); acc2_2[4]=fmaf(a11,v2j[1],acc2_2[4]); acc2_2[5]=fmaf(a11,v2j[2],acc2_2[5]);
                    acc2_2[6]=fmaf(a12,v2j[0],acc2_2[6]); acc2_2[7]=fmaf(a12,v2j[1],acc2_2[7]); acc2_2[8]=fmaf(a12,v2j[2],acc2_2[8]);
                }
            }

            // ---- write outputs (first half of the row) for both o's
            float* orow = out + (size_t)(row0 + slot) * ROW_IN;
            orow[o1] = acc0_1;
            orow[o2] = acc0_2;
            #pragma unroll
            for (int i = 0; i < 3; i++) {
                orow[16 + 3*o1 + i] = acc1_1[i];
                orow[16 + 3*o2 + i] = acc1_2[i];
            }
            #pragma unroll
            for (int k = 0; k < 9; k++) {
                orow[64 + 9*o1 + k] = acc2_1[k];
                orow[64 + 9*o2 + k] = acc2_2[k];
            }
        }

        // ---- zero the s=1 half (cols 208..415)
        {
            float4 z = make_float4(0.f, 0.f, 0.f, 0.f);
            float4* og = reinterpret_cast<float4*>(out) + (size_t)row0 * 104;
            for (int i = tid; i < nrows * 52; i += THREADS) {
                int r = i / 52, c = i - r * 52;
                og[(size_t)r * 104 + 52 + c] = z;
            }
        }
        __syncthreads();
    }
}

extern "C" void kernel_launch(void* const* d_in, const int* in_sizes, int n_in,
                              void* d_out, int out_size)
{
    const float* x1 = (const float*)d_in[0];
    const float* x2 = (const float*)d_in[1];
    const float* w  = (const float*)d_in[2];
    float* out = (float*)d_out;
    const int N = in_sizes[0] / ROW_IN;

    const int smem_bytes = (WSM + 2 * RPT * ROW_PAD) * (int)sizeof(float);

    int smcount = 0;
    cudaDeviceGetAttribute(&smcount, cudaDevAttrMultiProcessorCount, 0);
    if (smcount <= 0) smcount = 148;
    cudaFuncSetAttribute(tp_o3_kernel, cudaFuncAttributeMaxDynamicSharedMemorySize,
                         smem_bytes);

    tp_o3_kernel<<<smcount, THREADS, smem_bytes>>>(x1, x2, w, out, N);
}